// round 8
// baseline (speedup 1.0000x reference)
#include <cuda_runtime.h>
#include <math.h>
#include <stdint.h>

#define N_SEL 200000
#define EVN   100000
#define MEMD  100
#define RAWD  172
#define NB    128
#define NBLK  ((N_SEL + NB - 1) / NB)
#define NTHR  512
#define KCH   18            // 18 K-chunks of 32: cols [0,576), real K = 572
#define BROWS 408           // 400 weight rows + 8 zero pad

// ---- smem layout (bytes) ----
#define ASTRIDE   144                 // 36 floats per row
#define A_OFF(pb) ((pb) * 18432)      // 128 rows
#define B_OFF(pb) (36864 + (pb) * 58752)  // 408 rows
#define GID_OFF   154368
#define DST_OFF   154880
#define IDX_OFF   155392
#define VAL_OFF   155904
#define TREL_OFF  156416
#define RAWP_OFF  156928
#define SMEM_TOTAL 157952

// ---------------- small PTX helpers ----------------
__device__ __forceinline__ uint32_t smem_u32(const void* p) {
    uint32_t a;
    asm("{ .reg .u64 t; cvta.to.shared.u64 t, %1; cvt.u32.u64 %0, t; }" : "=r"(a) : "l"(p));
    return a;
}
__device__ __forceinline__ uint32_t tf32u(float x) {
    uint32_t u;
    asm("cvt.rna.tf32.f32 %0, %1;" : "=r"(u) : "f"(x));
    return u;
}
__device__ __forceinline__ void cp16(uint32_t dst, const void* src, uint32_t sz) {
    asm volatile("cp.async.cg.shared.global [%0], [%1], 16, %2;"
                 :: "r"(dst), "l"(src), "r"(sz) : "memory");
}
#define CP_COMMIT() asm volatile("cp.async.commit_group;" ::: "memory")
#define CP_WAIT0()  asm volatile("cp.async.wait_group 0;" ::: "memory")
#define CP_WAIT1()  asm volatile("cp.async.wait_group 1;" ::: "memory")

__device__ __forceinline__ void mma8(float* c, const uint32_t* a, uint32_t b0, uint32_t b1) {
    asm volatile("mma.sync.aligned.m16n8k8.row.col.f32.tf32.tf32.f32 "
                 "{%0,%1,%2,%3}, {%4,%5,%6,%7}, {%8,%9}, {%0,%1,%2,%3};"
                 : "+f"(c[0]), "+f"(c[1]), "+f"(c[2]), "+f"(c[3])
                 : "r"(a[0]), "r"(a[1]), "r"(a[2]), "r"(a[3]), "r"(b0), "r"(b1));
}

// ---------------- device scratch ----------------
__device__ unsigned long long g_win[N_SEL];
__device__ int g_cnt_valid;
__device__ int g_cnt_invalid;
__device__ int g_list[N_SEL];
__device__ float g_Bpk[BROWS * 576];   // prepacked, tf32-rounded, k8-group-permuted

// ---------------- aggregation ----------------
__global__ void k_init() {
    int i = blockIdx.x * blockDim.x + threadIdx.x;
    if (i < N_SEL) g_win[i] = 0ull;
    if (i == 0) { g_cnt_valid = 0; g_cnt_invalid = 0; }
}
__global__ void k_aggregate(const int* __restrict__ loc_s, const int* __restrict__ t_s,
                            const int* __restrict__ loc_d, const int* __restrict__ t_d) {
    int e = blockIdx.x * blockDim.x + threadIdx.x;
    if (e >= 2 * EVN) return;
    int loc, t;
    if (e < EVN) { loc = loc_s[e];       t = t_s[e]; }
    else         { loc = loc_d[e - EVN]; t = t_d[e - EVN]; }
    unsigned long long key = (((unsigned long long)(unsigned)(t + 1)) << 32) | (unsigned)e;
    atomicMax(&g_win[loc], key);
}
__global__ void k_partition() {
    int i = blockIdx.x * blockDim.x + threadIdx.x;
    if (i >= N_SEL) return;
    if (g_win[i] != 0ull) { int p = atomicAdd(&g_cnt_valid, 1);   g_list[p] = i; }
    else                  { int p = atomicAdd(&g_cnt_invalid, 1); g_list[N_SEL - 1 - p] = i; }
}

// ---------------- weight prepack: virtual B [408 x 576] ----------------
// Virtual matrix (row r, source col c):
//   r in [0,200):  c<472 -> W_ih[r][c]        ; c in [472,572) -> W_hh[r][c-472]
//   r in [200,300): c<472 -> W_ih[r][c] (i_n) ; else 0
//   r in [300,400): c in [472,572) -> W_hh[r-100][c-472] (h_n) ; else 0
//   r >= 400 or c >= 572: 0
// Column permutation within each 8-col group: output order [0,4,1,5,2,6,3,7]
// so the mma fragment pair (k0+t, k0+t+4) is contiguous -> LDS.64 in compute.
__global__ void k_prepack(const float* __restrict__ W_ih, const float* __restrict__ W_hh) {
    int idx = blockIdx.x * blockDim.x + threadIdx.x;
    if (idx >= BROWS * 576) return;
    int r = idx / 576, oc = idx - r * 576;
    int p = oc & 7;
    int c = (oc & ~7) + ((p & 1) ? ((p >> 1) + 4) : (p >> 1));   // source col
    float v = 0.f;
    if (r < 200) {
        if (c < 472) v = __ldg(&W_ih[(size_t)r * 472 + c]);
        else if (c < 572) v = __ldg(&W_hh[(size_t)r * MEMD + (c - 472)]);
    } else if (r < 300) {
        if (c < 472) v = __ldg(&W_ih[(size_t)r * 472 + c]);
    } else if (r < 400) {
        if (c >= 472 && c < 572) v = __ldg(&W_hh[(size_t)(r - 100) * MEMD + (c - 472)]);
    }
    g_Bpk[idx] = __uint_as_float(tf32u(v));
}

// ---------------- staging ----------------
__device__ __forceinline__ void stage_chunk(
    char* smem, uint32_t sm32, int kc, int pb, int tid,
    const float* __restrict__ memory,
    const float* __restrict__ time_w, const float* __restrict__ time_b,
    const int* s_gid, const int* s_dst, const float* const* s_raw,
    const float* s_trel, const int* s_val)
{
    const int q = tid & 7;
    const int c4 = kc * 32 + q * 4;      // global A column of this lane's float4
    // ---- A tile: 128 rows x 32 K ----
    #pragma unroll
    for (int mi = 0; mi < 2; mi++) {
        int m = (tid >> 3) + mi * 64;
        uint32_t dst = sm32 + A_OFF(pb) + m * ASTRIDE + q * 16;
        bool val = (s_val[m] != 0);
        if (c4 >= 372 && c4 < 472) {       // time-encoding: compute + STS
            float4 v = make_float4(0.f, 0.f, 0.f, 0.f);
            if (val) {
                int col = c4 - 372;
                float tr = s_trel[m];
                float4 w = __ldg((const float4*)(time_w + col));
                float4 b = __ldg((const float4*)(time_b + col));
                v.x = cosf(fmaf(tr, w.x, b.x));
                v.y = cosf(fmaf(tr, w.y, b.y));
                v.z = cosf(fmaf(tr, w.z, b.z));
                v.w = cosf(fmaf(tr, w.w, b.w));
            }
            *(float4*)(smem + A_OFF(pb) + m * ASTRIDE + q * 16) = v;
        } else {
            const float* src = memory; uint32_t sz = 0;
            if (c4 < 100)        { if (val) { src = memory + (size_t)s_gid[m] * MEMD + c4;          sz = 16; } }
            else if (c4 < 200)   { if (val) { src = memory + (size_t)s_dst[m] * MEMD + (c4 - 100);  sz = 16; } }
            else if (c4 < 372)   { if (val) { src = s_raw[m] + (c4 - 200);                           sz = 16; } }
            else if (c4 < 572)   { src = memory + (size_t)s_gid[m] * MEMD + (c4 - 472);              sz = 16; }
            cp16(dst, src, sz);  // sz=0 -> zero-fill (invalid rows / pad cols)
        }
    }
    // ---- B tile: dense copy from prepacked buffer (permutation preserved) ----
    const float* Bsrc = g_Bpk + kc * 32 + q * 4;
    for (int w = tid >> 3; w < BROWS; w += 64)
        cp16(sm32 + B_OFF(pb) + w * ASTRIDE + q * 16, Bsrc + (size_t)w * 576, 16);
}

// ---------------- per-chunk MMA (B pre-converted + pair-permuted -> LDS.64) ----------------
__device__ __forceinline__ void compute_chunk(
    const char* smem, int pb, int wm, int wn, int g, int t,
    float (&acc)[2][13][4])
{
    const float*    As = (const float*)(smem + A_OFF(pb)) + (wm * 32 + g) * 36 + t;
    const uint32_t* Bs = (const uint32_t*)(smem + B_OFF(pb)) + (wn * 100 + g) * 36 + 2 * t;
    #pragma unroll
    for (int ks = 0; ks < 4; ks++) {
        const int k0 = ks * 8;
        uint32_t a[2][4];
        #pragma unroll
        for (int mt = 0; mt < 2; mt++) {
            const float* Ap = As + mt * 16 * 36 + k0;
            a[mt][0] = tf32u(Ap[0]);
            a[mt][1] = tf32u(Ap[8 * 36]);
            a[mt][2] = tf32u(Ap[4]);
            a[mt][3] = tf32u(Ap[8 * 36 + 4]);
        }
        #pragma unroll
        for (int nt = 0; nt < 13; nt++) {
            uint2 b = *(const uint2*)(Bs + nt * 8 * 36 + k0);
            mma8(acc[0][nt], a[0], b.x, b.y);
            mma8(acc[1][nt], a[1], b.x, b.y);
        }
    }
}

// ---------------- main fused kernel ----------------
__global__ __launch_bounds__(NTHR, 1)
void k_main3(const float* __restrict__ memory, const int* __restrict__ last_update,
             const int* __restrict__ n_id,
             const int* __restrict__ dst_s, const float* __restrict__ raw_s,
             const int* __restrict__ dst_d, const float* __restrict__ raw_d,
             const float* __restrict__ time_w, const float* __restrict__ time_b,
             const float* __restrict__ b_ih, const float* __restrict__ b_hh,
             float* __restrict__ out_mem, float* __restrict__ out_lu, int write_lu)
{
    extern __shared__ __align__(128) char smem[];
    const uint32_t sm32 = smem_u32(smem);
    const int tid  = threadIdx.x;
    const int lane = tid & 31;
    const int wid  = tid >> 5;
    const int g = lane >> 2, t = lane & 3;
    const int wn = wid & 3, wm = wid >> 2;
    const int base = blockIdx.x * NB;

    int*   s_gid  = (int*)(smem + GID_OFF);
    int*   s_dst  = (int*)(smem + DST_OFF);
    int*   s_idx  = (int*)(smem + IDX_OFF);
    int*   s_val  = (int*)(smem + VAL_OFF);
    float* s_trel = (float*)(smem + TREL_OFF);
    const float** s_raw = (const float**)(smem + RAWP_OFF);

    const int nValid = g_cnt_valid;

    // ---- prologue: per-node metadata ----
    if (tid < NB) {
        int li = base + tid; if (li >= N_SEL) li = N_SEL - 1;
        int node = g_list[li];
        unsigned long long key = g_win[node];
        int gid = __ldg(&n_id[node]);
        int lu  = __ldg(&last_update[gid]);
        bool valid = (key != 0ull);
        int dst = 0, tt = 0; const float* raw = raw_s; float trel = 0.f;
        if (valid) {
            int e = (int)(key & 0xffffffffull);
            tt = (int)(key >> 32) - 1;
            if (e < EVN) { dst = __ldg(&dst_s[e]); raw = raw_s + (size_t)e * RAWD; }
            else { int e2 = e - EVN; dst = __ldg(&dst_d[e2]); raw = raw_d + (size_t)e2 * RAWD; }
            trel = (float)(tt - lu);
        }
        s_idx[tid] = node; s_gid[tid] = gid; s_dst[tid] = dst;
        s_raw[tid] = raw; s_trel[tid] = trel; s_val[tid] = valid ? 1 : 0;
        if (write_lu && base + tid < N_SEL)
            out_lu[node] = (float)(valid ? max(lu, tt) : lu);
    }
    __syncthreads();

    float acc[2][13][4];
    #pragma unroll
    for (int i = 0; i < 2; i++)
        #pragma unroll
        for (int j = 0; j < 13; j++)
            #pragma unroll
            for (int k = 0; k < 4; k++) acc[i][j][k] = 0.f;

    const int kc_start = (base < nValid) ? 0 : 14;

    stage_chunk(smem, sm32, kc_start, 0, tid, memory, time_w, time_b,
                s_gid, s_dst, s_raw, s_trel, s_val);
    CP_COMMIT();

    int it = 0;
    for (int kc = kc_start; kc < KCH; kc++, it++) {
        if (kc + 1 < KCH) {
            stage_chunk(smem, sm32, kc + 1, (it + 1) & 1, tid, memory,
                        time_w, time_b, s_gid, s_dst, s_raw, s_trel, s_val);
            CP_COMMIT();
            CP_WAIT1();
        } else {
            CP_WAIT0();
        }
        __syncthreads();
        compute_chunk(smem, it & 1, wm, wn, g, t, acc);
        __syncthreads();
    }

    // ---- epilogue: two 64-row passes through smem, GRU gates, write out ----
    float* Dp = (float*)smem;                 // 64 x 404 f32, reuses A/B buffers
    #pragma unroll
    for (int p = 0; p < 2; p++) {
        if ((wm >> 1) == p) {
            #pragma unroll
            for (int mt = 0; mt < 2; mt++) {
                int r0 = (wm & 1) * 32 + mt * 16 + g;
                #pragma unroll
                for (int nt = 0; nt < 13; nt++) {
                    int c = wn * 100 + nt * 8 + 2 * t;
                    Dp[r0 * 404 + c]           = acc[mt][nt][0];
                    Dp[r0 * 404 + c + 1]       = acc[mt][nt][1];
                    Dp[(r0 + 8) * 404 + c]     = acc[mt][nt][2];
                    Dp[(r0 + 8) * 404 + c + 1] = acc[mt][nt][3];
                }
            }
        }
        __syncthreads();
        for (int idx = tid; idx < 64 * MEMD; idx += NTHR) {
            int ml = idx / MEMD, c = idx - ml * MEMD;
            int m = p * 64 + ml;
            float r = Dp[ml * 404 + c]       + __ldg(&b_ih[c])       + __ldg(&b_hh[c]);
            float z = Dp[ml * 404 + 100 + c] + __ldg(&b_ih[100 + c]) + __ldg(&b_hh[100 + c]);
            r = 1.f / (1.f + expf(-r));
            z = 1.f / (1.f + expf(-z));
            float hn = Dp[ml * 404 + 300 + c] + __ldg(&b_hh[200 + c]);
            float n = tanhf(Dp[ml * 404 + 200 + c] + __ldg(&b_ih[200 + c]) + r * hn);
            float h = __ldg(memory + (size_t)s_gid[m] * MEMD + c);
            out_mem[(size_t)s_idx[m] * MEMD + c] = fmaf(z, h - n, n);
        }
        __syncthreads();
    }
}

// ---------------- launch ----------------
extern "C" void kernel_launch(void* const* d_in, const int* in_sizes, int n_in,
                              void* d_out, int out_size) {
    const float* memory      = (const float*)d_in[0];
    const int*   last_update = (const int*)  d_in[1];
    const int*   n_id        = (const int*)  d_in[2];
    const int*   loc_s       = (const int*)  d_in[3];
    const int*   dst_s       = (const int*)  d_in[4];
    const int*   t_s         = (const int*)  d_in[5];
    const float* raw_s       = (const float*)d_in[6];
    const int*   loc_d       = (const int*)  d_in[7];
    const int*   dst_d       = (const int*)  d_in[8];
    const int*   t_d         = (const int*)  d_in[9];
    const float* raw_d       = (const float*)d_in[10];
    const float* time_w      = (const float*)d_in[11];
    const float* time_b      = (const float*)d_in[12];
    const float* W_ih        = (const float*)d_in[13];
    const float* W_hh        = (const float*)d_in[14];
    const float* b_ih        = (const float*)d_in[15];
    const float* b_hh        = (const float*)d_in[16];

    float* out_mem = (float*)d_out;
    float* out_lu  = out_mem + (size_t)N_SEL * MEMD;
    int write_lu = (out_size >= N_SEL * MEMD + N_SEL) ? 1 : 0;

    cudaFuncSetAttribute(k_main3, cudaFuncAttributeMaxDynamicSharedMemorySize, SMEM_TOTAL);

    k_init     <<<(N_SEL + 255) / 256, 256>>>();
    k_aggregate<<<(2 * EVN + 255) / 256, 256>>>(loc_s, t_s, loc_d, t_d);
    k_partition<<<(N_SEL + 255) / 256, 256>>>();
    k_prepack  <<<(BROWS * 576 + 255) / 256, 256>>>(W_ih, W_hh);
    k_main3    <<<NBLK, NTHR, SMEM_TOTAL>>>(memory, last_update, n_id,
                                            dst_s, raw_s, dst_d, raw_d,
                                            time_w, time_b, b_ih, b_hh,
                                            out_mem, out_lu, write_lu);
}

// round 9
// speedup vs baseline: 1.2618x; 1.2618x over previous
#include <cuda_runtime.h>
#include <cuda_fp16.h>
#include <math.h>
#include <stdint.h>

#define N_SEL 200000
#define EVN   100000
#define MEMD  100
#define RAWD  172
#define NB    128
#define NBLK  ((N_SEL + NB - 1) / NB)
#define NTHR  512
#define KCH   9             // 9 K-chunks of 64 cols: [0,576), real K = 572
#define BROWS 408           // 400 weight rows + 8 zero pad

// ---- smem layout (bytes) ----
#define A_STRIDE  272                 // 64 f32 cols (256B) + 16B pad
#define B_STRIDE  144                 // 64 fp16 cols (128B) + 16B pad
#define A_OFF(pb) ((pb) * 34816)      // 128 rows x 272B
#define B_OFF(pb) (69632 + (pb) * 58752)  // 408 rows x 144B
#define GID_OFF   187136
#define DST_OFF   187648
#define IDX_OFF   188160
#define VAL_OFF   188672
#define TREL_OFF  189184
#define RAWP_OFF  189696
#define SMEM_TOTAL 190720

// ---------------- small PTX helpers ----------------
__device__ __forceinline__ uint32_t smem_u32(const void* p) {
    uint32_t a;
    asm("{ .reg .u64 t; cvta.to.shared.u64 t, %1; cvt.u32.u64 %0, t; }" : "=r"(a) : "l"(p));
    return a;
}
__device__ __forceinline__ uint32_t f16x2(float lo, float hi) {
    uint32_t d;
    asm("cvt.rn.f16x2.f32 %0, %1, %2;" : "=r"(d) : "f"(hi), "f"(lo));  // first src -> high half
    return d;
}
__device__ __forceinline__ void cp16(uint32_t dst, const void* src, uint32_t sz) {
    asm volatile("cp.async.cg.shared.global [%0], [%1], 16, %2;"
                 :: "r"(dst), "l"(src), "r"(sz) : "memory");
}
#define CP_COMMIT() asm volatile("cp.async.commit_group;" ::: "memory")
#define CP_WAIT0()  asm volatile("cp.async.wait_group 0;" ::: "memory")
#define CP_WAIT1()  asm volatile("cp.async.wait_group 1;" ::: "memory")

__device__ __forceinline__ void mma16(float* c, const uint32_t* a, uint32_t b0, uint32_t b1) {
    asm volatile("mma.sync.aligned.m16n8k16.row.col.f32.f16.f16.f32 "
                 "{%0,%1,%2,%3}, {%4,%5,%6,%7}, {%8,%9}, {%0,%1,%2,%3};"
                 : "+f"(c[0]), "+f"(c[1]), "+f"(c[2]), "+f"(c[3])
                 : "r"(a[0]), "r"(a[1]), "r"(a[2]), "r"(a[3]), "r"(b0), "r"(b1));
}

// ---------------- device scratch ----------------
__device__ unsigned long long g_win[N_SEL];
__device__ int g_cnt_valid;
__device__ int g_cnt_invalid;
__device__ int g_list[N_SEL];
__device__ uint32_t g_Bpk[BROWS * 288];   // fp16x2 words: [408 rows][288 words], k16-permuted

// ---------------- aggregation ----------------
__global__ void k_init() {
    int i = blockIdx.x * blockDim.x + threadIdx.x;
    if (i < N_SEL) g_win[i] = 0ull;
    if (i == 0) { g_cnt_valid = 0; g_cnt_invalid = 0; }
}
__global__ void k_aggregate(const int* __restrict__ loc_s, const int* __restrict__ t_s,
                            const int* __restrict__ loc_d, const int* __restrict__ t_d) {
    int e = blockIdx.x * blockDim.x + threadIdx.x;
    if (e >= 2 * EVN) return;
    int loc, t;
    if (e < EVN) { loc = loc_s[e];       t = t_s[e]; }
    else         { loc = loc_d[e - EVN]; t = t_d[e - EVN]; }
    unsigned long long key = (((unsigned long long)(unsigned)(t + 1)) << 32) | (unsigned)e;
    atomicMax(&g_win[loc], key);
}
__global__ void k_partition() {
    int i = blockIdx.x * blockDim.x + threadIdx.x;
    if (i >= N_SEL) return;
    if (g_win[i] != 0ull) { int p = atomicAdd(&g_cnt_valid, 1);   g_list[p] = i; }
    else                  { int p = atomicAdd(&g_cnt_invalid, 1); g_list[N_SEL - 1 - p] = i; }
}

// ---------------- weight prepack: virtual B [408 x 576] -> fp16, permuted ----------------
// Virtual matrix (row r, source col c):
//   r in [0,200):  c<472 -> W_ih[r][c]        ; c in [472,572) -> W_hh[r][c-472]
//   r in [200,300): c<472 -> W_ih[r][c] (i_n) ; else 0
//   r in [300,400): c in [472,572) -> W_hh[r-100][c-472] (h_n) ; else 0
//   r >= 400 or c >= 572: 0
// fp16x2 word w covers source cols (2w, 2w+1), lo = even col.
// Within each k16 group (8 words) output order [0,4,1,5,2,6,3,7] so the mma
// fragment pair (word t, word t+4) is contiguous -> one LDS.64 per B fragment.
__device__ __forceinline__ float bval(int r, int c, const float* W_ih, const float* W_hh) {
    float v = 0.f;
    if (r < 200) {
        if (c < 472) v = __ldg(&W_ih[(size_t)r * 472 + c]);
        else if (c < 572) v = __ldg(&W_hh[(size_t)r * MEMD + (c - 472)]);
    } else if (r < 300) {
        if (c < 472) v = __ldg(&W_ih[(size_t)r * 472 + c]);
    } else if (r < 400) {
        if (c >= 472 && c < 572) v = __ldg(&W_hh[(size_t)(r - 100) * MEMD + (c - 472)]);
    }
    return v;
}
__global__ void k_prepack(const float* __restrict__ W_ih, const float* __restrict__ W_hh) {
    int idx = blockIdx.x * blockDim.x + threadIdx.x;
    if (idx >= BROWS * 288) return;
    int r = idx / 288, ow = idx - r * 288;
    int grp = ow >> 3, p = ow & 7;
    int sw = (p & 1) ? ((p >> 1) + 4) : (p >> 1);      // source word within group
    int c0 = grp * 16 + sw * 2;
    __half2 hv = __floats2half2_rn(bval(r, c0, W_ih, W_hh), bval(r, c0 + 1, W_ih, W_hh));
    g_Bpk[idx] = *reinterpret_cast<uint32_t*>(&hv);
}

// ---------------- staging (A f32 cp.async + tenc STS; B fp16 dense cp.async) ----------------
__device__ __forceinline__ void stage_chunk(
    char* smem, uint32_t sm32, int kc, int pb, int tid,
    const float* __restrict__ memory,
    const float* __restrict__ time_w, const float* __restrict__ time_b,
    const int* s_gid, const int* s_dst, const float* const* s_raw,
    const float* s_trel, const int* s_val)
{
    // ---- A tile: 128 rows x 64 f32 cols ----
    const int q  = tid & 15;
    const int c4 = kc * 64 + q * 4;      // global A column of this lane's float4
    #pragma unroll
    for (int pass = 0; pass < 4; pass++) {
        int m = (tid >> 4) + pass * 32;
        uint32_t dst = sm32 + A_OFF(pb) + m * A_STRIDE + q * 16;
        bool val = (s_val[m] != 0);
        if (c4 >= 372 && c4 < 472) {       // time-encoding: compute + STS
            float4 v = make_float4(0.f, 0.f, 0.f, 0.f);
            if (val) {
                int col = c4 - 372;
                float tr = s_trel[m];
                float4 w = __ldg((const float4*)(time_w + col));
                float4 b = __ldg((const float4*)(time_b + col));
                v.x = cosf(fmaf(tr, w.x, b.x));
                v.y = cosf(fmaf(tr, w.y, b.y));
                v.z = cosf(fmaf(tr, w.z, b.z));
                v.w = cosf(fmaf(tr, w.w, b.w));
            }
            *(float4*)(smem + A_OFF(pb) + m * A_STRIDE + q * 16) = v;
        } else {
            const float* src = memory; uint32_t sz = 0;
            if (c4 < 100)        { if (val) { src = memory + (size_t)s_gid[m] * MEMD + c4;          sz = 16; } }
            else if (c4 < 200)   { if (val) { src = memory + (size_t)s_dst[m] * MEMD + (c4 - 100);  sz = 16; } }
            else if (c4 < 372)   { if (val) { src = s_raw[m] + (c4 - 200);                           sz = 16; } }
            else if (c4 < 572)   { src = memory + (size_t)s_gid[m] * MEMD + (c4 - 472);              sz = 16; }
            cp16(dst, src, sz);  // sz=0 -> zero-fill (invalid rows / pad cols)
        }
    }
    // ---- B tile: 408 rows x 64 fp16 cols (32 words = 128B/row) ----
    const int q8 = tid & 7;
    const uint32_t* Bsrc = g_Bpk + kc * 32 + q8 * 4;
    for (int w = tid >> 3; w < BROWS; w += 64)
        cp16(sm32 + B_OFF(pb) + w * B_STRIDE + q8 * 16, Bsrc + (size_t)w * 288, 16);
}

// ---------------- per-chunk MMA: fp16 m16n8k16, A cvt'd from f32 at load ----------------
__device__ __forceinline__ void compute_chunk(
    const char* smem, int pb, int wm, int wn, int g, int t,
    float (&acc)[2][13][4])
{
    const float*    As = (const float*)(smem + A_OFF(pb)) + (wm * 32 + g) * 68;
    const uint32_t* Bs = (const uint32_t*)(smem + B_OFF(pb)) + (wn * 100 + g) * 36 + 2 * t;
    #pragma unroll
    for (int ks = 0; ks < 4; ks++) {
        uint32_t a[2][4];
        #pragma unroll
        for (int mt = 0; mt < 2; mt++) {
            const float* Ap = As + mt * 16 * 68 + ks * 16;
            float2 v0 = *(const float2*)(Ap + 2 * t);              // row g,   k 2t..2t+1
            float2 v1 = *(const float2*)(Ap + 8 * 68 + 2 * t);     // row g+8
            float2 v2 = *(const float2*)(Ap + 2 * t + 8);          // row g,   k 2t+8..
            float2 v3 = *(const float2*)(Ap + 8 * 68 + 2 * t + 8); // row g+8
            a[mt][0] = f16x2(v0.x, v0.y);
            a[mt][1] = f16x2(v1.x, v1.y);
            a[mt][2] = f16x2(v2.x, v2.y);
            a[mt][3] = f16x2(v3.x, v3.y);
        }
        #pragma unroll
        for (int nt = 0; nt < 13; nt++) {
            uint2 b = *(const uint2*)(Bs + nt * 8 * 36 + ks * 8);
            mma16(acc[0][nt], a[0], b.x, b.y);
            mma16(acc[1][nt], a[1], b.x, b.y);
        }
    }
}

// ---------------- main fused kernel ----------------
__global__ __launch_bounds__(NTHR, 1)
void k_main3(const float* __restrict__ memory, const int* __restrict__ last_update,
             const int* __restrict__ n_id,
             const int* __restrict__ dst_s, const float* __restrict__ raw_s,
             const int* __restrict__ dst_d, const float* __restrict__ raw_d,
             const float* __restrict__ time_w, const float* __restrict__ time_b,
             const float* __restrict__ b_ih, const float* __restrict__ b_hh,
             float* __restrict__ out_mem, float* __restrict__ out_lu, int write_lu)
{
    extern __shared__ __align__(128) char smem[];
    const uint32_t sm32 = smem_u32(smem);
    const int tid  = threadIdx.x;
    const int lane = tid & 31;
    const int wid  = tid >> 5;
    const int g = lane >> 2, t = lane & 3;
    const int wn = wid & 3, wm = wid >> 2;
    const int base = blockIdx.x * NB;

    int*   s_gid  = (int*)(smem + GID_OFF);
    int*   s_dst  = (int*)(smem + DST_OFF);
    int*   s_idx  = (int*)(smem + IDX_OFF);
    int*   s_val  = (int*)(smem + VAL_OFF);
    float* s_trel = (float*)(smem + TREL_OFF);
    const float** s_raw = (const float**)(smem + RAWP_OFF);

    const int nValid = g_cnt_valid;

    // ---- prologue: per-node metadata ----
    if (tid < NB) {
        int li = base + tid; if (li >= N_SEL) li = N_SEL - 1;
        int node = g_list[li];
        unsigned long long key = g_win[node];
        int gid = __ldg(&n_id[node]);
        int lu  = __ldg(&last_update[gid]);
        bool valid = (key != 0ull);
        int dst = 0, tt = 0; const float* raw = raw_s; float trel = 0.f;
        if (valid) {
            int e = (int)(key & 0xffffffffull);
            tt = (int)(key >> 32) - 1;
            if (e < EVN) { dst = __ldg(&dst_s[e]); raw = raw_s + (size_t)e * RAWD; }
            else { int e2 = e - EVN; dst = __ldg(&dst_d[e2]); raw = raw_d + (size_t)e2 * RAWD; }
            trel = (float)(tt - lu);
        }
        s_idx[tid] = node; s_gid[tid] = gid; s_dst[tid] = dst;
        s_raw[tid] = raw; s_trel[tid] = trel; s_val[tid] = valid ? 1 : 0;
        if (write_lu && base + tid < N_SEL)
            out_lu[node] = (float)(valid ? max(lu, tt) : lu);
    }
    __syncthreads();

    float acc[2][13][4];
    #pragma unroll
    for (int i = 0; i < 2; i++)
        #pragma unroll
        for (int j = 0; j < 13; j++)
            #pragma unroll
            for (int k = 0; k < 4; k++) acc[i][j][k] = 0.f;

    // all-invalid blocks: only chunks covering h cols [472,572) -> kc 7,8
    // (chunk 7 also covers tenc cols 448-471, staged as zeros for invalid rows)
    const int kc_start = (base < nValid) ? 0 : 7;

    stage_chunk(smem, sm32, kc_start, 0, tid, memory, time_w, time_b,
                s_gid, s_dst, s_raw, s_trel, s_val);
    CP_COMMIT();

    int it = 0;
    for (int kc = kc_start; kc < KCH; kc++, it++) {
        if (kc + 1 < KCH) {
            stage_chunk(smem, sm32, kc + 1, (it + 1) & 1, tid, memory,
                        time_w, time_b, s_gid, s_dst, s_raw, s_trel, s_val);
            CP_COMMIT();
            CP_WAIT1();
        } else {
            CP_WAIT0();
        }
        __syncthreads();
        compute_chunk(smem, it & 1, wm, wn, g, t, acc);
        __syncthreads();
    }

    // ---- epilogue: two 64-row passes through smem, GRU gates, write out ----
    float* Dp = (float*)smem;                 // 64 x 404 f32, reuses A/B buffers
    #pragma unroll
    for (int p = 0; p < 2; p++) {
        if ((wm >> 1) == p) {
            #pragma unroll
            for (int mt = 0; mt < 2; mt++) {
                int r0 = (wm & 1) * 32 + mt * 16 + g;
                #pragma unroll
                for (int nt = 0; nt < 13; nt++) {
                    int c = wn * 100 + nt * 8 + 2 * t;
                    Dp[r0 * 404 + c]           = acc[mt][nt][0];
                    Dp[r0 * 404 + c + 1]       = acc[mt][nt][1];
                    Dp[(r0 + 8) * 404 + c]     = acc[mt][nt][2];
                    Dp[(r0 + 8) * 404 + c + 1] = acc[mt][nt][3];
                }
            }
        }
        __syncthreads();
        for (int idx = tid; idx < 64 * MEMD; idx += NTHR) {
            int ml = idx / MEMD, c = idx - ml * MEMD;
            int m = p * 64 + ml;
            float r = Dp[ml * 404 + c]       + __ldg(&b_ih[c])       + __ldg(&b_hh[c]);
            float z = Dp[ml * 404 + 100 + c] + __ldg(&b_ih[100 + c]) + __ldg(&b_hh[100 + c]);
            r = 1.f / (1.f + expf(-r));
            z = 1.f / (1.f + expf(-z));
            float hn = Dp[ml * 404 + 300 + c] + __ldg(&b_hh[200 + c]);
            float n = tanhf(Dp[ml * 404 + 200 + c] + __ldg(&b_ih[200 + c]) + r * hn);
            float h = __ldg(memory + (size_t)s_gid[m] * MEMD + c);
            out_mem[(size_t)s_idx[m] * MEMD + c] = fmaf(z, h - n, n);
        }
        __syncthreads();
    }
}

// ---------------- launch ----------------
extern "C" void kernel_launch(void* const* d_in, const int* in_sizes, int n_in,
                              void* d_out, int out_size) {
    const float* memory      = (const float*)d_in[0];
    const int*   last_update = (const int*)  d_in[1];
    const int*   n_id        = (const int*)  d_in[2];
    const int*   loc_s       = (const int*)  d_in[3];
    const int*   dst_s       = (const int*)  d_in[4];
    const int*   t_s         = (const int*)  d_in[5];
    const float* raw_s       = (const float*)d_in[6];
    const int*   loc_d       = (const int*)  d_in[7];
    const int*   dst_d       = (const int*)  d_in[8];
    const int*   t_d         = (const int*)  d_in[9];
    const float* raw_d       = (const float*)d_in[10];
    const float* time_w      = (const float*)d_in[11];
    const float* time_b      = (const float*)d_in[12];
    const float* W_ih        = (const float*)d_in[13];
    const float* W_hh        = (const float*)d_in[14];
    const float* b_ih        = (const float*)d_in[15];
    const float* b_hh        = (const float*)d_in[16];

    float* out_mem = (float*)d_out;
    float* out_lu  = out_mem + (size_t)N_SEL * MEMD;
    int write_lu = (out_size >= N_SEL * MEMD + N_SEL) ? 1 : 0;

    cudaFuncSetAttribute(k_main3, cudaFuncAttributeMaxDynamicSharedMemorySize, SMEM_TOTAL);

    k_init     <<<(N_SEL + 255) / 256, 256>>>();
    k_aggregate<<<(2 * EVN + 255) / 256, 256>>>(loc_s, t_s, loc_d, t_d);
    k_partition<<<(N_SEL + 255) / 256, 256>>>();
    k_prepack  <<<(BROWS * 288 + 255) / 256, 256>>>(W_ih, W_hh);
    k_main3    <<<NBLK, NTHR, SMEM_TOTAL>>>(memory, last_update, n_id,
                                            dst_s, raw_s, dst_d, raw_d,
                                            time_w, time_b, b_ih, b_hh,
                                            out_mem, out_lu, write_lu);
}